// round 15
// baseline (speedup 1.0000x reference)
#include <cuda_runtime.h>

#define BB 64
#define HH 14
#define WWD 14
#define HW 196
#define CC 32
#define OO 10
#define NCH 7               // hw-chunks per batch
#define HWB 28              // hw positions per block
#define TPB 320             // 10 warps: warp = o, lane = c
#define EPSF 1e-9f
#define LOG2PI 1.8378770664093453f

typedef unsigned long long u64;

// ---- f32x2 packed math (Blackwell) ---------------------------------------
__device__ __forceinline__ u64 pack2(float lo, float hi) {
    u64 r; asm("mov.b64 %0, {%1,%2};" : "=l"(r) : "f"(lo), "f"(hi)); return r;
}
__device__ __forceinline__ u64 pdup(float x) { return pack2(x, x); }
__device__ __forceinline__ void unpack2(u64 v, float& lo, float& hi) {
    asm("mov.b64 {%0,%1}, %2;" : "=f"(lo), "=f"(hi) : "l"(v));
}
__device__ __forceinline__ u64 fma2(u64 a, u64 b, u64 c) {
    u64 d; asm("fma.rn.f32x2 %0,%1,%2,%3;" : "=l"(d) : "l"(a), "l"(b), "l"(c)); return d;
}
__device__ __forceinline__ u64 mul2(u64 a, u64 b) {
    u64 d; asm("mul.rn.f32x2 %0,%1,%2;" : "=l"(d) : "l"(a), "l"(b)); return d;
}
__device__ __forceinline__ u64 add2(u64 a, u64 b) {
    u64 d; asm("add.rn.f32x2 %0,%1,%2;" : "=l"(d) : "l"(a), "l"(b)); return d;
}

// Scratch (fully rewritten every replay -> deterministic, graph-safe)
__device__ float g_partials[BB*NCH*OO*33]; // [b][chunk][o][S0,S1[16],S2[16]]
__device__ float g_params[BB*OO*33];       // [b][o][K, ivar[16], muinv[16]]
__device__ int   g_cnt[3*BB];              // per-phase counters (winner resets)
__device__ int   g_flag[2*BB];             // per-phase release flags (final winner resets)

// ---- vote computation (shared by all phases) ------------------------------
__device__ __forceinline__ void compute_votes(const float4* row, const u64 wv[4][2],
                                              int hw, u64 v[8])
{
    const int h    = hw / WWD;
    const int wpos = hw - h * WWD;
    #pragma unroll
    for (int i = 0; i < 4; i++) {
        const float4 P = row[i];
        const u64 p0 = pdup(P.x), p1 = pdup(P.y), p2 = pdup(P.z), p3 = pdup(P.w);
        v[i*2+0] = fma2(p0, wv[0][0], fma2(p1, wv[1][0],
                   fma2(p2, wv[2][0], mul2(p3, wv[3][0]))));
        v[i*2+1] = fma2(p0, wv[0][1], fma2(p1, wv[1][1],
                   fma2(p2, wv[2][1], mul2(p3, wv[3][1]))));
    }
    v[1] = add2(v[1], pack2(0.f, (wpos + 0.5f) * (1.0f / WWD)));
    v[3] = add2(v[3], pack2(0.f, (h    + 0.5f) * (1.0f / HH)));
}

// ---- warp-reduce S over 32 c's and store partials -------------------------
__device__ __forceinline__ void store_partials(int b, int ch, int o, int c,
                                               float S0, u64 S1[8], u64 S2[8])
{
    #pragma unroll
    for (int off = 16; off > 0; off >>= 1) {
        S0 += __shfl_xor_sync(0xFFFFFFFFu, S0, off);
        #pragma unroll
        for (int k = 0; k < 8; k++) {
            u64 a1 = __shfl_xor_sync(0xFFFFFFFFu, S1[k], off);
            u64 a2 = __shfl_xor_sync(0xFFFFFFFFu, S2[k], off);
            S1[k] = add2(S1[k], a1);
            S2[k] = add2(S2[k], a2);
        }
    }
    if (c == 0) {
        float* dst = g_partials + (size_t)((b * NCH + ch) * OO + o) * 33;
        dst[0] = S0;
        #pragma unroll
        for (int k = 0; k < 8; k++) {
            float lo, hi;
            unpack2(S1[k], lo, hi);
            dst[1 + 2*k] = lo;  dst[2 + 2*k] = hi;
            unpack2(S2[k], lo, hi);
            dst[17 + 2*k] = lo; dst[18 + 2*k] = hi;
        }
    }
}

// ---- winner: reduce partials -> params (or final outputs) -----------------
__device__ __forceinline__ void winner_work(int b, int tid, float inv_temp, bool final_out,
                                            const float* __restrict__ beta_a,
                                            const float* __restrict__ beta_u,
                                            float* __restrict__ out)
{
    if (tid < OO * 16) {
        const int ro = tid >> 4;
        const int rd = tid & 15;

        float R0 = 0.f, R1 = 0.f, R2 = 0.f;
        #pragma unroll
        for (int g = 0; g < NCH; g++) {
            const float* p = g_partials + (size_t)((b * NCH + g) * OO + ro) * 33;
            R0 += __ldcg(p);
            R1 += __ldcg(p + 1 + rd);
            R2 += __ldcg(p + 17 + rd);
        }

        const float rs     = R0 + EPSF;
        const float inv_rs = 1.0f / rs;
        const float mu     = R1 * inv_rs;
        const float var    = fmaxf(R2 * inv_rs - mu * mu, 0.0f) + EPSF;
        const float lv     = __logf(var);
        const float ivar   = 1.0f / var;
        const float muinv  = mu * ivar;
        const float mive   = mu * muinv;

        float sumlv = lv, summive = mive;
        #pragma unroll
        for (int off = 1; off < 16; off <<= 1) {
            sumlv   += __shfl_xor_sync(0xFFFFFFFFu, sumlv,   off);
            summive += __shfl_xor_sync(0xFFFFFFFFu, summive, off);
        }

        const float cost = rs * (16.0f * beta_u[ro] + 0.5f * sumlv);
        const float x    = inv_temp * (beta_a[ro] - cost);
        const float actv = 1.0f / (1.0f + __expf(-x));

        if (final_out) {
            out[(size_t)(b * OO + ro) * 16 + rd] = mu;
            if (rd == 0) out[BB * OO * 16 + b * OO + ro] = actv;
        } else {
            float* pp = g_params + (size_t)(b * OO + ro) * 33;
            pp[1 + rd]  = ivar;
            pp[17 + rd] = muinv;
            if (rd == 0)
                pp[0] = __logf(actv + EPSF)
                      - 0.5f * (16.0f * LOG2PI + sumlv)
                      - 0.5f * summive;
        }
    }
}

// ===========================================================================
// Fully-fused EM: one kernel, 3 phases, per-batch counter/flag sync.
// Dynamic smem: sp4 71680 | prm 1280 | ss 1536 | se 1536 | sa 3584 | Ksm/swin.
// ===========================================================================
#define SMEM_ALL (71680 + 1280 + 1536 + 1536 + 3584 + 64)

__global__ void __launch_bounds__(TPB, 2)
caps_all(const float* __restrict__ pose,
         const float* __restrict__ act,
         const float* __restrict__ w,
         const float* __restrict__ beta_a,
         const float* __restrict__ beta_u,
         float* __restrict__ out)
{
    extern __shared__ char smraw[];
    float4* sp4 = (float4*)smraw;                        // [28][32][5]
    float4* prm = (float4*)(smraw + 71680);              // [OO*8]
    float*  ss  = (float*)(smraw + 71680 + 1280);        // [32*12]
    float*  se  = ss + 32 * 12;                          // [32*12]
    float*  sa  = se + 32 * 12;                          // [28*32]
    float*  Ksm = sa + HWB * 32;                         // [OO]
    int*    swin = (int*)(Ksm + OO + 2);

    const int b   = blockIdx.y;
    const int ch  = blockIdx.x;
    const int hw0 = ch * HWB;
    const int tid = threadIdx.x;
    const int o   = tid >> 5;
    const int c   = tid & 31;

    // ---- prologue: tile load (once for all three passes) ------------------
    {
        const float4* src4 = (const float4*)(pose + (size_t)(b * HW + hw0) * CC * 16);
        for (int idx = tid; idx < HWB * CC * 4; idx += TPB) {
            const int t_l = idx >> 7;
            const int rem = idx & 127;
            sp4[(t_l * 32 + (rem >> 2)) * 5 + (rem & 3)] = src4[idx];
        }
        const float* asrc = act + (size_t)(b * HW + hw0) * CC;
        for (int idx = tid; idx < HWB * CC; idx += TPB)
            sa[idx] = asrc[idx];
    }

    // per-thread w[c][o], rows packed as column pairs
    u64 wv[4][2];
    {
        const float4* wp = (const float4*)(w + (size_t)(c * OO + o) * 16);
        #pragma unroll
        for (int j = 0; j < 4; j++) {
            const float4 r = wp[j];
            wv[j][0] = pack2(r.x, r.y);
            wv[j][1] = pack2(r.z, r.w);
        }
    }
    __syncthreads();

    // ======================= PHASE A: pass 0 (rr = 1/O) ====================
    {
        float S0 = 0.f;
        u64 S1[8], S2[8];
        #pragma unroll
        for (int k = 0; k < 8; k++) { S1[k] = 0ull; S2[k] = 0ull; }

        for (int t = 0; t < HWB; t++) {
            u64 v[8];
            compute_votes(sp4 + (t * 32 + c) * 5, wv, hw0 + t, v);
            const float ap = 0.1f * sa[t * 32 + c];
            S0 += ap;
            const u64 ap2 = pdup(ap);
            #pragma unroll
            for (int k = 0; k < 8; k++) {
                const u64 t1 = mul2(ap2, v[k]);
                S1[k] = add2(S1[k], t1);
                S2[k] = fma2(t1, v[k], S2[k]);
            }
        }
        store_partials(b, ch, o, c, S0, S1, S2);

        __threadfence();
        __syncthreads();
        if (tid == 0) {
            int prev = atomicAdd(&g_cnt[b], 1);
            *swin = (prev == NCH - 1);
        }
        __syncthreads();
        if (*swin) {
            if (tid == 0) g_cnt[b] = 0;
            winner_work(b, tid, 1.0f, false, beta_a, beta_u, out);
        }
        __threadfence();
        __syncthreads();
        if (*swin && tid == 0) atomicExch(&g_flag[b], 1);
        if (tid == 0) { while (atomicAdd(&g_flag[b], 0) == 0) __nanosleep(64); }
        __syncthreads();
        __threadfence();   // invalidate L1 before param reads
    }

    // =================== PHASES B (it=1) and C (it=2) ======================
    #pragma unroll 1
    for (int phase = 1; phase <= 2; phase++) {
        const float inv_temp = (phase == 1) ? 2.0f : 3.0f;
        const bool  final_out = (phase == 2);

        // load params (L2, bypass possibly-stale L1)
        if (tid < OO * 8) {
            const int po = tid >> 3, pk = tid & 7;
            const float* pp = g_params + (size_t)(b * OO + po) * 33;
            prm[po * 8 + pk] = make_float4(__ldcg(pp + 1 + 2*pk), __ldcg(pp + 2 + 2*pk),
                                           __ldcg(pp + 17 + 2*pk), __ldcg(pp + 18 + 2*pk));
        }
        if (tid < OO) Ksm[tid] = __ldcg(&g_params[(size_t)(b * OO + tid) * 33]);
        __syncthreads();
        const float K = Ksm[o];

        float S0 = 0.f;
        u64 S1[8], S2[8];
        #pragma unroll
        for (int k = 0; k < 8; k++) { S1[k] = 0ull; S2[k] = 0ull; }

        for (int t = 0; t < HWB; t++) {
            u64 v[8];
            compute_votes(sp4 + (t * 32 + c) * 5, wv, hw0 + t, v);

            u64 e1 = 0ull, e2 = 0ull;
            #pragma unroll
            for (int k = 0; k < 8; k++) {
                const longlong2 q = *(const longlong2*)&prm[o * 8 + k];   // uniform
                e1 = fma2(mul2(v[k], v[k]), (u64)q.x, e1);
                e2 = fma2(v[k], (u64)q.y, e2);
            }
            float e1l, e1h, e2l, e2h;
            unpack2(e1, e1l, e1h);
            unpack2(e2, e2l, e2h);
            const float s = fmaf(-0.5f, e1l + e1h, K + e2l + e2h);

            ss[c * 12 + o] = s;
            __syncthreads();
            const float4 q0 = *(const float4*)(ss + c * 12);
            const float4 q1 = *(const float4*)(ss + c * 12 + 4);
            const float2 q2 = *(const float2*)(ss + c * 12 + 8);
            const float mx = fmaxf(fmaxf(fmaxf(fmaxf(q0.x, q0.y), fmaxf(q0.z, q0.w)),
                                   fmaxf(fmaxf(q1.x, q1.y), fmaxf(q1.z, q1.w))),
                                   fmaxf(q2.x, q2.y));
            const float e = __expf(s - mx);
            se[c * 12 + o] = e;
            __syncthreads();
            const float4 r0 = *(const float4*)(se + c * 12);
            const float4 r1 = *(const float4*)(se + c * 12 + 4);
            const float2 r2 = *(const float2*)(se + c * 12 + 8);
            const float den = (((r0.x + r0.y) + (r0.z + r0.w))
                             + ((r1.x + r1.y) + (r1.z + r1.w))) + (r2.x + r2.y);
            const float ap = sa[t * 32 + c] * __fdividef(e, den);

            S0 += ap;
            const u64 ap2 = pdup(ap);
            #pragma unroll
            for (int k = 0; k < 8; k++) {
                const u64 t1 = mul2(ap2, v[k]);
                S1[k] = add2(S1[k], t1);
                S2[k] = fma2(t1, v[k], S2[k]);
            }
        }
        store_partials(b, ch, o, c, S0, S1, S2);

        __threadfence();
        __syncthreads();
        if (tid == 0) {
            int prev = atomicAdd(&g_cnt[phase * BB + b], 1);
            *swin = (prev == NCH - 1);
        }
        __syncthreads();

        if (phase == 1) {
            if (*swin) {
                if (tid == 0) g_cnt[BB + b] = 0;
                winner_work(b, tid, inv_temp, false, beta_a, beta_u, out);
            }
            __threadfence();
            __syncthreads();
            if (*swin && tid == 0) atomicExch(&g_flag[BB + b], 1);
            if (tid == 0) { while (atomicAdd(&g_flag[BB + b], 0) == 0) __nanosleep(64); }
            __syncthreads();
            __threadfence();
        } else {
            if (*swin) {
                if (tid == 0) g_cnt[2 * BB + b] = 0;
                winner_work(b, tid, inv_temp, true, beta_a, beta_u, out);
                __syncthreads();
                if (tid == 0) {            // restore flags for next graph replay
                    atomicExch(&g_flag[b], 0);
                    atomicExch(&g_flag[BB + b], 0);
                }
            }
        }
    }
}

// ---------------------------------------------------------------------------
extern "C" void kernel_launch(void* const* d_in, const int* in_sizes, int n_in,
                              void* d_out, int out_size)
{
    const float* pose = (const float*)d_in[0];
    const float* act  = (const float*)d_in[1];
    const float* w    = (const float*)d_in[2];
    const float* ba   = (const float*)d_in[3];
    const float* bu   = (const float*)d_in[4];
    float* out = (float*)d_out;

    static int smem_set = 0;
    if (!smem_set) {   // driver state only; capture-safe
        cudaFuncSetAttribute(caps_all, cudaFuncAttributeMaxDynamicSharedMemorySize, SMEM_ALL);
        smem_set = 1;
    }

    dim3 ga(NCH, BB);
    caps_all<<<ga, TPB, SMEM_ALL>>>(pose, act, w, ba, bu, out);
}